// round 10
// baseline (speedup 1.0000x reference)
#include <cuda_runtime.h>
#include <cuda_fp16.h>
#include <cstdint>
#include <math.h>

// ---------------------------------------------------------------------------
// B=4, Q=K=4096, D=IN=256.
// R10: R9 flash pipeline + ldmatrix.x4 fragment loads (flash + hgemm were
// LDS-issue-bound), merged cvt launches, ballot-gated O rescale.
// ---------------------------------------------------------------------------

__device__ __half g_xq[4u * 4096u * 256u];
__device__ __half g_xk[4u * 4096u * 256u];
__device__ __half g_xv[4u * 4096u * 256u];
__device__ __half g_wq[65536], g_wk[65536], g_wv[65536], g_wo[65536];
__device__ __half g_qh[4u * 4096u * 256u];
__device__ __half g_kh[4u * 4096u * 256u];
__device__ __half g_vh[4u * 4096u * 256u];
__device__ __half g_vth[4u * 4096u * 256u];
__device__ __half g_atth[4u * 4096u * 256u];

// ======================= helpers =======================
__device__ __forceinline__ uint32_t smem_u32(const void* p) {
  uint32_t a;
  asm("{ .reg .u64 t; cvta.to.shared.u64 t, %1; cvt.u32.u64 %0, t; }"
      : "=r"(a) : "l"(p));
  return a;
}
__device__ __forceinline__ void cp16(uint32_t s, const void* g) {
  asm volatile("cp.async.cg.shared.global [%0], [%1], 16;\n" ::"r"(s), "l"(g));
}
__device__ __forceinline__ void cp_commit() {
  asm volatile("cp.async.commit_group;\n" ::: "memory");
}
template <int N>
__device__ __forceinline__ void cp_wait() {
  asm volatile("cp.async.wait_group %0;\n" ::"n"(N) : "memory");
}
__device__ __forceinline__ void mma16(float* d, const uint32_t* a, const uint32_t* b) {
  asm volatile(
      "mma.sync.aligned.m16n8k16.row.col.f32.f16.f16.f32 "
      "{%0,%1,%2,%3}, {%4,%5,%6,%7}, {%8,%9}, {%0,%1,%2,%3};"
      : "+f"(d[0]), "+f"(d[1]), "+f"(d[2]), "+f"(d[3])
      : "r"(a[0]), "r"(a[1]), "r"(a[2]), "r"(a[3]), "r"(b[0]), "r"(b[1]));
}
__device__ __forceinline__ void ldsm4(uint32_t* r, uint32_t addr) {
  asm volatile(
      "ldmatrix.sync.aligned.m8n8.x4.shared.b16 {%0,%1,%2,%3}, [%4];"
      : "=r"(r[0]), "=r"(r[1]), "=r"(r[2]), "=r"(r[3]) : "r"(addr));
}
__device__ __forceinline__ uint32_t pack_half2(float a, float b) {
  __half2 h = __floats2half2_rn(a, b);
  return *(uint32_t*)&h;
}
__device__ __forceinline__ void store2(float* p, float d0, float d1) {
  float2 v; v.x = d0; v.y = d1;
  *(float2*)p = v;
}
__device__ __forceinline__ void store2(__half* p, float d0, float d1) {
  *(__half2*)p = __floats2half2_rn(d0, d1);
}

// ---------------------------------------------------------------------------
// fp16 GEMM: C[M,N] = A[M,Kd] @ B[N,Kd]^T (+ bias). ldmatrix fragment loads.
// CTA 128x128, BK=32, 8 warps (2m x 4n), warp tile 64x32.
// Smem rows: 32 halves + 8 words pad = 80B/row (conflict-free for LDSM).
// ---------------------------------------------------------------------------
#define S32 20
#define TILE_WORDS (128 * S32)
#define TILE_BYTES_G (TILE_WORDS * 4)       // 10240
#define STAGE_BYTES (2 * TILE_BYTES_G)      // 20480
#define GEMM_SMEM (2 * STAGE_BYTES)         // 40960

template <bool BIAS, typename OutT>
__global__ void __launch_bounds__(256, 2) hgemm(
    const __half* __restrict__ A, const __half* __restrict__ B,
    const float* __restrict__ bias, OutT* __restrict__ C,
    int Kd, int ldA, int ldB, int ldC,
    long long sA, long long sB, long long sC) {
  extern __shared__ char dyn_smem[];
  const uint32_t smem_base = smem_u32(dyn_smem);
  const int tid = threadIdx.x;
  const int lane = tid & 31;
  const int wid = tid >> 5;
  const int wm = wid & 1;
  const int wn = wid >> 1;
  const long long z = blockIdx.z;
  const int bm = blockIdx.y * 128;
  const int bn = blockIdx.x * 128;

  const __half* gA = A + z * sA + (size_t)bm * ldA;
  const __half* gB = B + z * sB + (size_t)bn * ldB;

  float acc[4][4][4];
#pragma unroll
  for (int i = 0; i < 4; i++)
#pragma unroll
    for (int j = 0; j < 4; j++)
#pragma unroll
      for (int p = 0; p < 4; p++) acc[i][j][p] = 0.0f;

  const int ldRow = tid & 127;
  const bool isB = tid >= 128;
  const __half* gRowBase = (isB ? gB : gA);
  const int ldLd = isB ? ldB : ldA;
  const uint32_t sRowOff = (isB ? TILE_BYTES_G : 0) + ldRow * (S32 * 4);

  auto load_tiles = [&](int stage, int k0) {
    const uint32_t s0 = smem_base + stage * STAGE_BYTES + sRowOff;
    const __half* g0 = gRowBase + (size_t)ldRow * ldLd + k0;
#pragma unroll
    for (int ch = 0; ch < 4; ch++) cp16(s0 + ch * 16, g0 + ch * 8);
    cp_commit();
  };

  // ldmatrix per-lane bases (A-type and B-type mappings)
  const uint32_t aRel = (uint32_t)(wm * 64 + (lane & 15)) * 80 + ((lane & 16) ? 16 : 0);
  const uint32_t bRel = TILE_BYTES_G +
      (uint32_t)(wn * 32 + ((lane & 16) ? 8 : 0) + (lane & 7)) * 80 +
      ((lane & 8) ? 16 : 0);

  const int KT = Kd >> 5;
  load_tiles(0, 0);
  for (int it = 0; it < KT; ++it) {
    const int buf = it & 1;
    if (it + 1 < KT) {
      load_tiles(buf ^ 1, (it + 1) << 5);
      cp_wait<1>();
    } else {
      cp_wait<0>();
    }
    __syncthreads();

    const uint32_t stg = smem_base + buf * STAGE_BYTES;
#pragma unroll
    for (int kk = 0; kk < 2; ++kk) {
      uint32_t af[4][4];
#pragma unroll
      for (int mt = 0; mt < 4; mt++)
        ldsm4(af[mt], stg + aRel + mt * (16 * 80) + kk * 32);
#pragma unroll
      for (int ntp = 0; ntp < 2; ntp++) {
        uint32_t b[4];
        ldsm4(b, stg + bRel + ntp * (16 * 80) + kk * 32);
#pragma unroll
        for (int mt = 0; mt < 4; mt++) {
          mma16(acc[mt][2 * ntp], af[mt], b);
          mma16(acc[mt][2 * ntp + 1], af[mt], b + 2);
        }
      }
    }
    __syncthreads();
  }

  OutT* Cz = C + z * sC;
  const int g = lane >> 2;
  const int c2 = (lane & 3) * 2;
#pragma unroll
  for (int mt = 0; mt < 4; mt++) {
    const int row0 = bm + wm * 64 + mt * 16 + g;
#pragma unroll
    for (int nt = 0; nt < 4; nt++) {
      const int col = bn + wn * 32 + nt * 8 + c2;
      float d0 = acc[mt][nt][0], d1 = acc[mt][nt][1];
      float d2 = acc[mt][nt][2], d3 = acc[mt][nt][3];
      if (BIAS) {
        const float b0 = bias[col], b1 = bias[col + 1];
        d0 += b0; d1 += b1; d2 += b0; d3 += b1;
      }
      store2(Cz + (size_t)row0 * ldC + col, d0, d1);
      store2(Cz + (size_t)(row0 + 8) * ldC + col, d2, d3);
    }
  }
}

// ---------------------------------------------------------------------------
// Flash attention with ldmatrix fragment loads.
// Per CTA: 128 q-rows x 4096 keys in 64-key tiles; 8 warps x 16 rows.
// smem: Q 128x528B + K 2x 64x528B + V 2x 256x144B = 208896 B.
// ---------------------------------------------------------------------------
#define OFF_Q 0
#define OFF_K0 (128 * 528)
#define OFF_K1 (OFF_K0 + 64 * 528)
#define OFF_V0 (OFF_K1 + 64 * 528)
#define OFF_V1 (OFF_V0 + 256 * 144)
#define FLASH_SMEM (OFF_V1 + 256 * 144)

__global__ void __launch_bounds__(256, 1) flash_attn(
    const __half* __restrict__ qh, const __half* __restrict__ kh,
    const __half* __restrict__ vth, const int* __restrict__ mask,
    __half* __restrict__ atth) {
  extern __shared__ char sm[];
  const uint32_t sb = smem_u32(sm);
  const int tid = threadIdx.x;
  const int lane = tid & 31;
  const int w = tid >> 5;
  const int g = lane >> 2;
  const int c = lane & 3;
  const int z = blockIdx.y;
  const int bm = blockIdx.x * 128;

  const __half* qp = qh + ((size_t)z * 4096 + bm) * 256;
  const __half* kp = kh + (size_t)z * 4096 * 256;
  const __half* vp = vth + (size_t)z * 256 * 4096;

  __shared__ int s_ctamax;
  if (tid == 0) s_ctamax = 0;
  __syncthreads();

  const int lenA = mask[z * 4096 + bm + w * 16 + g];
  const int lenB = mask[z * 4096 + bm + w * 16 + 8 + g];
  int wmax = max(lenA, lenB);
#pragma unroll
  for (int o = 4; o < 32; o <<= 1) wmax = max(wmax, __shfl_xor_sync(0xffffffffu, wmax, o));
  if (lane == 0) atomicMax(&s_ctamax, wmax);

#pragma unroll
  for (int i = 0; i < 16; i++) {
    const int idx = tid + i * 256;
    const int row = idx >> 5, ch = idx & 31;
    cp16(sb + OFF_Q + row * 528 + ch * 16, qp + (size_t)row * 256 + ch * 8);
  }
  cp_commit();

  auto load_kv = [&](int stage, int kt) {
    const uint32_t ko = sb + (stage ? OFF_K1 : OFF_K0);
    const uint32_t vo = sb + (stage ? OFF_V1 : OFF_V0);
#pragma unroll
    for (int i = 0; i < 8; i++) {
      const int idx = tid + i * 256;
      const int row = idx >> 5, ch = idx & 31;
      cp16(ko + row * 528 + ch * 16, kp + (size_t)(kt * 64 + row) * 256 + ch * 8);
    }
#pragma unroll
    for (int i = 0; i < 8; i++) {
      const int idx = tid + i * 256;
      const int row = idx >> 3, ch = idx & 7;
      cp16(vo + row * 144 + ch * 16, vp + (size_t)row * 4096 + kt * 64 + ch * 8);
    }
    cp_commit();
  };

  load_kv(0, 0);
  __syncthreads();
  const int NT = (s_ctamax + 63) >> 6;

  // ldmatrix per-lane bases
  const uint32_t qBase = sb + OFF_Q +
      (uint32_t)(w * 16 + (lane & 15)) * 528 + ((lane & 16) ? 16 : 0);
  const uint32_t bRowSel = ((lane & 16) ? 8 : 0) + (lane & 7);
  const uint32_t bOffSel = (lane & 8) ? 16 : 0;
  const uint32_t kRel = bRowSel * 528 + bOffSel;
  const uint32_t vRel = bRowSel * 144 + bOffSel;

  float O[32][4];
#pragma unroll
  for (int i = 0; i < 32; i++)
#pragma unroll
    for (int j = 0; j < 4; j++) O[i][j] = 0.0f;
  float m0 = -1e30f, m1 = -1e30f, l0 = 0.0f, l1 = 0.0f;

  for (int kt = 0; kt < NT; kt++) {
    const int buf = kt & 1;
    if (kt + 1 < NT) {
      load_kv(buf ^ 1, kt + 1);
      cp_wait<1>();
    } else {
      cp_wait<0>();
    }
    __syncthreads();

    if (kt * 64 < wmax) {
      // ---- S = Q @ K^T ----
      float S[8][4];
#pragma unroll
      for (int nt = 0; nt < 8; nt++)
#pragma unroll
        for (int j = 0; j < 4; j++) S[nt][j] = 0.0f;

      const uint32_t kst = sb + (buf ? OFF_K1 : OFF_K0) + kRel;
#pragma unroll
      for (int ks = 0; ks < 16; ks++) {
        uint32_t a[4];
        ldsm4(a, qBase + ks * 32);
#pragma unroll
        for (int ntp = 0; ntp < 4; ntp++) {
          uint32_t b[4];
          ldsm4(b, kst + ntp * (16 * 528) + ks * 32);
          mma16(S[2 * ntp], a, b);
          mma16(S[2 * ntp + 1], a, b + 2);
        }
      }

      // ---- mask + scale + online softmax ----
      const int kb = kt * 64;
      float tmax0 = -1e30f, tmax1 = -1e30f;
#pragma unroll
      for (int nt = 0; nt < 8; nt++) {
        const int col0 = kb + nt * 8 + c * 2;
        const int col1 = col0 + 1;
        float s00 = (col0 < lenA) ? S[nt][0] * 0.0625f : -1e30f;
        float s01 = (col1 < lenA) ? S[nt][1] * 0.0625f : -1e30f;
        float s10 = (col0 < lenB) ? S[nt][2] * 0.0625f : -1e30f;
        float s11 = (col1 < lenB) ? S[nt][3] * 0.0625f : -1e30f;
        S[nt][0] = s00; S[nt][1] = s01; S[nt][2] = s10; S[nt][3] = s11;
        tmax0 = fmaxf(tmax0, fmaxf(s00, s01));
        tmax1 = fmaxf(tmax1, fmaxf(s10, s11));
      }
      tmax0 = fmaxf(tmax0, __shfl_xor_sync(0xffffffffu, tmax0, 1));
      tmax0 = fmaxf(tmax0, __shfl_xor_sync(0xffffffffu, tmax0, 2));
      tmax1 = fmaxf(tmax1, __shfl_xor_sync(0xffffffffu, tmax1, 1));
      tmax1 = fmaxf(tmax1, __shfl_xor_sync(0xffffffffu, tmax1, 2));

      const float mn0 = fmaxf(m0, tmax0), mn1 = fmaxf(m1, tmax1);
      const bool changed = (mn0 > m0) || (mn1 > m1);
      float al0 = 1.0f, al1 = 1.0f;
      if (__ballot_sync(0xffffffffu, changed)) {
        al0 = __expf(m0 - mn0);
        al1 = __expf(m1 - mn1);
#pragma unroll
        for (int nt2 = 0; nt2 < 32; nt2++) {
          O[nt2][0] *= al0; O[nt2][1] *= al0;
          O[nt2][2] *= al1; O[nt2][3] *= al1;
        }
      }
      m0 = mn0; m1 = mn1;

      float sum0 = 0.0f, sum1 = 0.0f;
#pragma unroll
      for (int nt = 0; nt < 8; nt++) {
        S[nt][0] = __expf(S[nt][0] - mn0);
        S[nt][1] = __expf(S[nt][1] - mn0);
        S[nt][2] = __expf(S[nt][2] - mn1);
        S[nt][3] = __expf(S[nt][3] - mn1);
        sum0 += S[nt][0] + S[nt][1];
        sum1 += S[nt][2] + S[nt][3];
      }
      sum0 += __shfl_xor_sync(0xffffffffu, sum0, 1);
      sum0 += __shfl_xor_sync(0xffffffffu, sum0, 2);
      sum1 += __shfl_xor_sync(0xffffffffu, sum1, 1);
      sum1 += __shfl_xor_sync(0xffffffffu, sum1, 2);
      l0 = l0 * al0 + sum0;
      l1 = l1 * al1 + sum1;

      // ---- P fragments (C-layout -> A-fragment) ----
      uint32_t pa[4][4];
#pragma unroll
      for (int ks2 = 0; ks2 < 4; ks2++) {
        pa[ks2][0] = pack_half2(S[2 * ks2][0], S[2 * ks2][1]);
        pa[ks2][1] = pack_half2(S[2 * ks2][2], S[2 * ks2][3]);
        pa[ks2][2] = pack_half2(S[2 * ks2 + 1][0], S[2 * ks2 + 1][1]);
        pa[ks2][3] = pack_half2(S[2 * ks2 + 1][2], S[2 * ks2 + 1][3]);
      }

      // ---- O += P @ V ----
      const uint32_t vst = sb + (buf ? OFF_V1 : OFF_V0) + vRel;
#pragma unroll
      for (int ks2 = 0; ks2 < 4; ks2++) {
#pragma unroll
        for (int ntp = 0; ntp < 16; ntp++) {
          uint32_t b[4];
          ldsm4(b, vst + ntp * (16 * 144) + ks2 * 32);
          mma16(O[2 * ntp], pa[ks2], b);
          mma16(O[2 * ntp + 1], pa[ks2], b + 2);
        }
      }
    }
    __syncthreads();
  }

  const float il0 = 1.0f / l0;
  const float il1 = 1.0f / l1;
  __half* op = atth + ((size_t)z * 4096 + bm + w * 16) * 256;
#pragma unroll
  for (int nt2 = 0; nt2 < 32; nt2++) {
    const int col = nt2 * 8 + c * 2;
    store2(op + (size_t)g * 256 + col, O[nt2][0] * il0, O[nt2][1] * il0);
    store2(op + (size_t)(g + 8) * 256 + col, O[nt2][2] * il1, O[nt2][3] * il1);
  }
}

// ---------------------------------------------------------------------------
// Merged fp32 -> fp16 conversion: 7 jobs in one launch (blockIdx.y selects).
// ---------------------------------------------------------------------------
__global__ __launch_bounds__(256) void cvt_multi(
    const float* s0, __half* d0, int n0, const float* s1, __half* d1, int n1,
    const float* s2, __half* d2, int n2, const float* s3, __half* d3, int n3,
    const float* s4, __half* d4, int n4_, const float* s5, __half* d5, int n5,
    const float* s6, __half* d6, int n6) {
  const float* ss[7] = {s0, s1, s2, s3, s4, s5, s6};
  __half* dd[7] = {d0, d1, d2, d3, d4, d5, d6};
  const int nn[7] = {n0, n1, n2, n3, n4_, n5, n6};
  const int j = blockIdx.y;
  const int i = blockIdx.x * blockDim.x + threadIdx.x;
  if (i < nn[j]) {
    float4 f = ((const float4*)ss[j])[i];
    ((__half2*)dd[j])[2 * i] = __floats2half2_rn(f.x, f.y);
    ((__half2*)dd[j])[2 * i + 1] = __floats2half2_rn(f.z, f.w);
  }
}

// ---------------------------------------------------------------------------
// Batched transpose (half): vt[b][n][k] = v[b][k][n]
// ---------------------------------------------------------------------------
__global__ __launch_bounds__(256) void transpose_h(
    const __half* __restrict__ v, __half* __restrict__ vt) {
  __shared__ __half t[32][33];
  const int b = blockIdx.z;
  const int k0 = blockIdx.x * 32;
  const int n0 = blockIdx.y * 32;
  const int tx = threadIdx.x & 31;
  const int ty = threadIdx.x >> 5;
  const __half* src = v + (size_t)b * 4096 * 256;
  __half* dst = vt + (size_t)b * 256 * 4096;
#pragma unroll
  for (int i = 0; i < 32; i += 8)
    t[ty + i][tx] = src[(size_t)(k0 + ty + i) * 256 + n0 + tx];
  __syncthreads();
#pragma unroll
  for (int i = 0; i < 32; i += 8)
    dst[(size_t)(n0 + ty + i) * 4096 + k0 + tx] = t[tx][ty + i];
}

// ---------------------------------------------------------------------------
// Launch
// ---------------------------------------------------------------------------
extern "C" void kernel_launch(void* const* d_in, const int* in_sizes, int n_in,
                              void* d_out, int out_size) {
  const float* queries = (const float*)d_in[0];
  const float* keys    = (const float*)d_in[1];
  const float* values  = (const float*)d_in[2];
  const int*   mask    = (const int*)d_in[3];
  const float* Wq = (const float*)d_in[4];
  const float* bq = (const float*)d_in[5];
  const float* Wk = (const float*)d_in[6];
  const float* bk = (const float*)d_in[7];
  const float* Wv = (const float*)d_in[8];
  const float* bv = (const float*)d_in[9];
  const float* Wo = (const float*)d_in[10];
  const float* bo = (const float*)d_in[11];
  float* out = (float*)d_out;

  __half *xq, *xk, *xv, *wq, *wk, *wv, *wo;
  __half *qh, *kh, *vh, *vth, *atth;
  cudaGetSymbolAddress((void**)&xq, g_xq);
  cudaGetSymbolAddress((void**)&xk, g_xk);
  cudaGetSymbolAddress((void**)&xv, g_xv);
  cudaGetSymbolAddress((void**)&wq, g_wq);
  cudaGetSymbolAddress((void**)&wk, g_wk);
  cudaGetSymbolAddress((void**)&wv, g_wv);
  cudaGetSymbolAddress((void**)&wo, g_wo);
  cudaGetSymbolAddress((void**)&qh, g_qh);
  cudaGetSymbolAddress((void**)&kh, g_kh);
  cudaGetSymbolAddress((void**)&vh, g_vh);
  cudaGetSymbolAddress((void**)&vth, g_vth);
  cudaGetSymbolAddress((void**)&atth, g_atth);

  cudaFuncSetAttribute(hgemm<true, __half>,
                       cudaFuncAttributeMaxDynamicSharedMemorySize, GEMM_SMEM);
  cudaFuncSetAttribute(hgemm<true, float>,
                       cudaFuncAttributeMaxDynamicSharedMemorySize, GEMM_SMEM);
  cudaFuncSetAttribute(flash_attn,
                       cudaFuncAttributeMaxDynamicSharedMemorySize, FLASH_SMEM);

  dim3 blk(256);
  const int NTOK4 = 4 * 4096 * 256 / 4;  // 1,048,576
  const int NW4 = 65536 / 4;             // 16,384

  // all fp32 -> fp16 in one launch
  cvt_multi<<<dim3(NTOK4 / 256, 7), blk>>>(
      queries, xq, NTOK4, keys, xk, NTOK4, values, xv, NTOK4,
      Wq, wq, NW4, Wk, wk, NW4, Wv, wv, NW4, Wo, wo, NW4);

  // Projections -> half
  dim3 gProj(2, 128, 1);
  hgemm<true, __half><<<gProj, blk, GEMM_SMEM>>>(
      xq, wq, bq, qh, 256, 256, 256, 256, 0, 0, 0);
  hgemm<true, __half><<<gProj, blk, GEMM_SMEM>>>(
      xk, wk, bk, kh, 256, 256, 256, 256, 0, 0, 0);
  hgemm<true, __half><<<gProj, blk, GEMM_SMEM>>>(
      xv, wv, bv, vh, 256, 256, 256, 256, 0, 0, 0);

  // vT for flash V tiles
  transpose_h<<<dim3(128, 8, 4), blk>>>(vh, vth);

  // Fused attention
  flash_attn<<<dim3(32, 4, 1), blk, FLASH_SMEM>>>(qh, kh, vth, mask, atth);

  // Output projection -> fp32
  hgemm<true, float><<<gProj, blk, GEMM_SMEM>>>(
      atth, wo, bo, out, 256, 256, 256, 256, 0, 0, 0);
}

// round 12
// speedup vs baseline: 1.1914x; 1.1914x over previous
#include <cuda_runtime.h>
#include <cuda_fp16.h>
#include <cstdint>
#include <math.h>

// ---------------------------------------------------------------------------
// B=4, Q=K=4096, D=IN=256.
// R11 = R9 (proven 357us) + length-sorted query scheduling for flash:
//   counting-sort queries by mask length per batch (perm), flash processes
//   rows in sorted order (gather q, scatter O) so warps/CTAs see near-equal
//   lengths -> attention work drops from ~94% of full to ~E[len] ~52%.
// R10's ldmatrix experiment regressed (357->434) and is fully reverted.
// ---------------------------------------------------------------------------

__device__ __half g_xq[4u * 4096u * 256u];
__device__ __half g_xk[4u * 4096u * 256u];
__device__ __half g_xv[4u * 4096u * 256u];
__device__ __half g_wq[65536], g_wk[65536], g_wv[65536], g_wo[65536];
__device__ __half g_qh[4u * 4096u * 256u];
__device__ __half g_kh[4u * 4096u * 256u];
__device__ __half g_vh[4u * 4096u * 256u];
__device__ __half g_vth[4u * 4096u * 256u];
__device__ __half g_atth[4u * 4096u * 256u];
__device__ int g_start[4 * 4096];
__device__ int g_perm[4 * 4096];

// ======================= helpers =======================
__device__ __forceinline__ uint32_t smem_u32(const void* p) {
  uint32_t a;
  asm("{ .reg .u64 t; cvta.to.shared.u64 t, %1; cvt.u32.u64 %0, t; }"
      : "=r"(a) : "l"(p));
  return a;
}
__device__ __forceinline__ void cp16(uint32_t s, const void* g) {
  asm volatile("cp.async.cg.shared.global [%0], [%1], 16;\n" ::"r"(s), "l"(g));
}
__device__ __forceinline__ void cp_commit() {
  asm volatile("cp.async.commit_group;\n" ::: "memory");
}
template <int N>
__device__ __forceinline__ void cp_wait() {
  asm volatile("cp.async.wait_group %0;\n" ::"n"(N) : "memory");
}
__device__ __forceinline__ void mma16(float* d, const uint32_t* a, const uint32_t* b) {
  asm volatile(
      "mma.sync.aligned.m16n8k16.row.col.f32.f16.f16.f32 "
      "{%0,%1,%2,%3}, {%4,%5,%6,%7}, {%8,%9}, {%0,%1,%2,%3};"
      : "+f"(d[0]), "+f"(d[1]), "+f"(d[2]), "+f"(d[3])
      : "r"(a[0]), "r"(a[1]), "r"(a[2]), "r"(a[3]), "r"(b[0]), "r"(b[1]));
}
__device__ __forceinline__ uint32_t pack_half2(float a, float b) {
  __half2 h = __floats2half2_rn(a, b);
  return *(uint32_t*)&h;
}
__device__ __forceinline__ void store2(float* p, float d0, float d1) {
  float2 v; v.x = d0; v.y = d1;
  *(float2*)p = v;
}
__device__ __forceinline__ void store2(__half* p, float d0, float d1) {
  *(__half2*)p = __floats2half2_rn(d0, d1);
}

// ---------------------------------------------------------------------------
// Counting sort of queries by mask length (per batch).
// sort_hist_scan: one 1024-thread CTA per batch; smem histogram (4096 bins,
// bin = len-1) + Hillis-Steele block scan -> g_start[z][bin] = exclusive base.
// sort_scatter: pos = g_start[bin]++ (atomic); g_perm[z][pos] = row index.
// Output values are invariant to within-bin order (see R11 note), so the
// atomic order nondeterminism is benign.
// ---------------------------------------------------------------------------
__global__ __launch_bounds__(1024) void sort_hist_scan(
    const int* __restrict__ mask, int* __restrict__ start) {
  __shared__ int hist[4096];
  __shared__ int sums[1024];
  __shared__ int sums2[1024];
  const int z = blockIdx.x;
  const int t = threadIdx.x;
#pragma unroll
  for (int i = 0; i < 4; i++) hist[t + i * 1024] = 0;
  __syncthreads();
#pragma unroll
  for (int i = 0; i < 4; i++)
    atomicAdd(&hist[mask[z * 4096 + t + i * 1024] - 1], 1);
  __syncthreads();
  const int c0 = hist[4 * t], c1 = hist[4 * t + 1];
  const int c2 = hist[4 * t + 2], c3 = hist[4 * t + 3];
  sums[t] = c0 + c1 + c2 + c3;
  __syncthreads();
  int* src = sums;
  int* dst = sums2;
  for (int off = 1; off < 1024; off <<= 1) {
    int v = src[t];
    if (t >= off) v += src[t - off];
    dst[t] = v;
    __syncthreads();
    int* tmp = src; src = dst; dst = tmp;
  }
  const int excl = (t == 0) ? 0 : src[t - 1];
  start[z * 4096 + 4 * t] = excl;
  start[z * 4096 + 4 * t + 1] = excl + c0;
  start[z * 4096 + 4 * t + 2] = excl + c0 + c1;
  start[z * 4096 + 4 * t + 3] = excl + c0 + c1 + c2;
}

__global__ __launch_bounds__(256) void sort_scatter(
    const int* __restrict__ mask, int* __restrict__ start,
    int* __restrict__ perm) {
  const int z = blockIdx.y;
  const int i = blockIdx.x * 256 + threadIdx.x;
  const int len = mask[z * 4096 + i];
  const int pos = atomicAdd(&start[z * 4096 + len - 1], 1);
  perm[z * 4096 + pos] = i;
}

// ---------------------------------------------------------------------------
// fp16 GEMM (R7/R9 proven): C[M,N] = A[M,Kd] @ B[N,Kd]^T (+ bias)
// ---------------------------------------------------------------------------
#define S32 20
#define TILE_WORDS (128 * S32)
#define STAGE_BYTES (2 * TILE_WORDS * 4)
#define GEMM_SMEM (2 * STAGE_BYTES)

template <bool BIAS, typename OutT>
__global__ void __launch_bounds__(256, 2) hgemm(
    const __half* __restrict__ A, const __half* __restrict__ B,
    const float* __restrict__ bias, OutT* __restrict__ C,
    int Kd, int ldA, int ldB, int ldC,
    long long sA, long long sB, long long sC) {
  extern __shared__ char dyn_smem[];
  const uint32_t smem_base = smem_u32(dyn_smem);
  const int tid = threadIdx.x;
  const int lane = tid & 31;
  const int wid = tid >> 5;
  const int wm = wid & 1;
  const int wn = wid >> 1;
  const long long z = blockIdx.z;
  const int bm = blockIdx.y * 128;
  const int bn = blockIdx.x * 128;

  const __half* gA = A + z * sA + (size_t)bm * ldA;
  const __half* gB = B + z * sB + (size_t)bn * ldB;

  float acc[4][4][4];
#pragma unroll
  for (int i = 0; i < 4; i++)
#pragma unroll
    for (int j = 0; j < 4; j++)
#pragma unroll
      for (int p = 0; p < 4; p++) acc[i][j][p] = 0.0f;

  const int ldRow = tid & 127;
  const bool isB = tid >= 128;
  const __half* gRowBase = (isB ? gB : gA);
  const int ldLd = isB ? ldB : ldA;
  const uint32_t sRowOff = (isB ? STAGE_BYTES / 2 : 0) + ldRow * (S32 * 4);

  auto load_tiles = [&](int stage, int k0) {
    const uint32_t s0 = smem_base + stage * STAGE_BYTES + sRowOff;
    const __half* g0 = gRowBase + (size_t)ldRow * ldLd + k0;
#pragma unroll
    for (int ch = 0; ch < 4; ch++) cp16(s0 + ch * 16, g0 + ch * 8);
    cp_commit();
  };

  const int g = lane >> 2;
  const int c = lane & 3;

  const int KT = Kd >> 5;
  load_tiles(0, 0);
  for (int it = 0; it < KT; ++it) {
    const int buf = it & 1;
    if (it + 1 < KT) {
      load_tiles(buf ^ 1, (it + 1) << 5);
      cp_wait<1>();
    } else {
      cp_wait<0>();
    }
    __syncthreads();

    const uint32_t* As32 = (const uint32_t*)(dyn_smem + buf * STAGE_BYTES);
    const uint32_t* Bs32 = As32 + TILE_WORDS;

#pragma unroll
    for (int kk = 0; kk < 2; ++kk) {
      const int ko = kk * 8;
      uint32_t af[4][4], bf[4][2];
#pragma unroll
      for (int mt = 0; mt < 4; mt++) {
        const int base = (wm * 64 + mt * 16 + g) * S32 + c + ko;
        af[mt][0] = As32[base];
        af[mt][1] = As32[base + 8 * S32];
        af[mt][2] = As32[base + 4];
        af[mt][3] = As32[base + 8 * S32 + 4];
      }
#pragma unroll
      for (int nt = 0; nt < 4; nt++) {
        const int base = (wn * 32 + nt * 8 + g) * S32 + c + ko;
        bf[nt][0] = Bs32[base];
        bf[nt][1] = Bs32[base + 4];
      }
#pragma unroll
      for (int mt = 0; mt < 4; mt++)
#pragma unroll
        for (int nt = 0; nt < 4; nt++) mma16(acc[mt][nt], af[mt], bf[nt]);
    }
    __syncthreads();
  }

  OutT* Cz = C + z * sC;
  const int c2 = c * 2;
#pragma unroll
  for (int mt = 0; mt < 4; mt++) {
    const int row0 = bm + wm * 64 + mt * 16 + g;
#pragma unroll
    for (int nt = 0; nt < 4; nt++) {
      const int col = bn + wn * 32 + nt * 8 + c2;
      float d0 = acc[mt][nt][0], d1 = acc[mt][nt][1];
      float d2 = acc[mt][nt][2], d3 = acc[mt][nt][3];
      if (BIAS) {
        const float b0 = bias[col], b1 = bias[col + 1];
        d0 += b0; d1 += b1; d2 += b0; d3 += b1;
      }
      store2(Cz + (size_t)row0 * ldC + col, d0, d1);
      store2(Cz + (size_t)(row0 + 8) * ldC + col, d2, d3);
    }
  }
}

// ---------------------------------------------------------------------------
// Flash attention (R9 core) with length-sorted query permutation.
// Per CTA: 128 permuted q-rows x keys in 64-key tiles; 8 warps x 16 rows.
// Q gathered via perm; O scattered back to original rows.
// smem: Q 128x528B + K 2x 64x528B + V 2x 256x144B = 208896 B.
// ---------------------------------------------------------------------------
#define OFF_Q 0
#define OFF_K0 (128 * 528)
#define OFF_K1 (OFF_K0 + 64 * 528)
#define OFF_V0 (OFF_K1 + 64 * 528)
#define OFF_V1 (OFF_V0 + 256 * 144)
#define FLASH_SMEM (OFF_V1 + 256 * 144)

__global__ void __launch_bounds__(256, 1) flash_attn(
    const __half* __restrict__ qh, const __half* __restrict__ kh,
    const __half* __restrict__ vth, const int* __restrict__ mask,
    const int* __restrict__ perm, __half* __restrict__ atth) {
  extern __shared__ char sm[];
  const uint32_t sb = smem_u32(sm);
  const int tid = threadIdx.x;
  const int lane = tid & 31;
  const int w = tid >> 5;
  const int g = lane >> 2;
  const int c = lane & 3;
  const int z = blockIdx.y;
  const int bm = blockIdx.x * 128;

  const __half* qp = qh + (size_t)z * 4096 * 256;
  const __half* kp = kh + (size_t)z * 4096 * 256;
  const __half* vp = vth + (size_t)z * 256 * 4096;
  const int* permz = perm + z * 4096 + bm;

  __shared__ int s_ctamax;
  if (tid == 0) s_ctamax = 0;
  __syncthreads();

  const int qiA = permz[w * 16 + g];
  const int qiB = permz[w * 16 + 8 + g];
  const int lenA = mask[z * 4096 + qiA];
  const int lenB = mask[z * 4096 + qiB];
  int wmax = max(lenA, lenB);
#pragma unroll
  for (int o = 4; o < 32; o <<= 1) wmax = max(wmax, __shfl_xor_sync(0xffffffffu, wmax, o));
  if (lane == 0) atomicMax(&s_ctamax, wmax);

  // Q tile (gathered): 128 rows x 512B (stride 528B)
#pragma unroll
  for (int i = 0; i < 16; i++) {
    const int idx = tid + i * 256;
    const int row = idx >> 5, ch = idx & 31;
    const int qrow = permz[row];
    cp16(sb + OFF_Q + row * 528 + ch * 16, qp + (size_t)qrow * 256 + ch * 8);
  }
  cp_commit();

  auto load_kv = [&](int stage, int kt) {
    const uint32_t ko = sb + (stage ? OFF_K1 : OFF_K0);
    const uint32_t vo = sb + (stage ? OFF_V1 : OFF_V0);
#pragma unroll
    for (int i = 0; i < 8; i++) {
      const int idx = tid + i * 256;
      const int row = idx >> 5, ch = idx & 31;
      cp16(ko + row * 528 + ch * 16, kp + (size_t)(kt * 64 + row) * 256 + ch * 8);
    }
#pragma unroll
    for (int i = 0; i < 8; i++) {
      const int idx = tid + i * 256;
      const int row = idx >> 3, ch = idx & 7;
      cp16(vo + row * 144 + ch * 16, vp + (size_t)row * 4096 + kt * 64 + ch * 8);
    }
    cp_commit();
  };

  load_kv(0, 0);
  __syncthreads();  // s_ctamax visible
  const int NT = (s_ctamax + 63) >> 6;

  float O[32][4];
#pragma unroll
  for (int i = 0; i < 32; i++)
#pragma unroll
    for (int j = 0; j < 4; j++) O[i][j] = 0.0f;
  float m0 = -1e30f, m1 = -1e30f, l0 = 0.0f, l1 = 0.0f;

  for (int kt = 0; kt < NT; kt++) {
    const int buf = kt & 1;
    if (kt + 1 < NT) {
      load_kv(buf ^ 1, kt + 1);
      cp_wait<1>();
    } else {
      cp_wait<0>();
    }
    __syncthreads();

    if (kt * 64 < wmax) {
      // ---- S = Q @ K^T (16 rows x 64 keys per warp) ----
      float S[8][4];
#pragma unroll
      for (int nt = 0; nt < 8; nt++)
#pragma unroll
        for (int j = 0; j < 4; j++) S[nt][j] = 0.0f;

      const uint32_t* Qs = (const uint32_t*)(sm + OFF_Q) + (w * 16 + g) * 132 + c;
      const uint32_t* Ks =
          (const uint32_t*)(sm + (buf ? OFF_K1 : OFF_K0)) + g * 132 + c;
#pragma unroll
      for (int ks = 0; ks < 16; ks++) {
        uint32_t a[4];
        a[0] = Qs[ks * 8];
        a[1] = Qs[ks * 8 + 8 * 132];
        a[2] = Qs[ks * 8 + 4];
        a[3] = Qs[ks * 8 + 8 * 132 + 4];
#pragma unroll
        for (int nt = 0; nt < 8; nt++) {
          uint32_t b[2];
          b[0] = Ks[nt * 8 * 132 + ks * 8];
          b[1] = Ks[nt * 8 * 132 + ks * 8 + 4];
          mma16(S[nt], a, b);
        }
      }

      // ---- mask + scale(1/16) + online softmax ----
      const int kb = kt * 64;
      float tmax0 = -1e30f, tmax1 = -1e30f;
#pragma unroll
      for (int nt = 0; nt < 8; nt++) {
        const int col0 = kb + nt * 8 + c * 2;
        const int col1 = col0 + 1;
        float s00 = (col0 < lenA) ? S[nt][0] * 0.0625f : -1e30f;
        float s01 = (col1 < lenA) ? S[nt][1] * 0.0625f : -1e30f;
        float s10 = (col0 < lenB) ? S[nt][2] * 0.0625f : -1e30f;
        float s11 = (col1 < lenB) ? S[nt][3] * 0.0625f : -1e30f;
        S[nt][0] = s00; S[nt][1] = s01; S[nt][2] = s10; S[nt][3] = s11;
        tmax0 = fmaxf(tmax0, fmaxf(s00, s01));
        tmax1 = fmaxf(tmax1, fmaxf(s10, s11));
      }
      tmax0 = fmaxf(tmax0, __shfl_xor_sync(0xffffffffu, tmax0, 1));
      tmax0 = fmaxf(tmax0, __shfl_xor_sync(0xffffffffu, tmax0, 2));
      tmax1 = fmaxf(tmax1, __shfl_xor_sync(0xffffffffu, tmax1, 1));
      tmax1 = fmaxf(tmax1, __shfl_xor_sync(0xffffffffu, tmax1, 2));

      const float mn0 = fmaxf(m0, tmax0), mn1 = fmaxf(m1, tmax1);
      const float al0 = __expf(m0 - mn0), al1 = __expf(m1 - mn1);
      m0 = mn0; m1 = mn1;

      float sum0 = 0.0f, sum1 = 0.0f;
#pragma unroll
      for (int nt = 0; nt < 8; nt++) {
        S[nt][0] = __expf(S[nt][0] - mn0);
        S[nt][1] = __expf(S[nt][1] - mn0);
        S[nt][2] = __expf(S[nt][2] - mn1);
        S[nt][3] = __expf(S[nt][3] - mn1);
        sum0 += S[nt][0] + S[nt][1];
        sum1 += S[nt][2] + S[nt][3];
      }
      sum0 += __shfl_xor_sync(0xffffffffu, sum0, 1);
      sum0 += __shfl_xor_sync(0xffffffffu, sum0, 2);
      sum1 += __shfl_xor_sync(0xffffffffu, sum1, 1);
      sum1 += __shfl_xor_sync(0xffffffffu, sum1, 2);
      l0 = l0 * al0 + sum0;
      l1 = l1 * al1 + sum1;

#pragma unroll
      for (int nt2 = 0; nt2 < 32; nt2++) {
        O[nt2][0] *= al0; O[nt2][1] *= al0;
        O[nt2][2] *= al1; O[nt2][3] *= al1;
      }

      // ---- P fragments (C-layout -> A-fragment) ----
      uint32_t pa[4][4];
#pragma unroll
      for (int ks2 = 0; ks2 < 4; ks2++) {
        pa[ks2][0] = pack_half2(S[2 * ks2][0], S[2 * ks2][1]);
        pa[ks2][1] = pack_half2(S[2 * ks2][2], S[2 * ks2][3]);
        pa[ks2][2] = pack_half2(S[2 * ks2 + 1][0], S[2 * ks2 + 1][1]);
        pa[ks2][3] = pack_half2(S[2 * ks2 + 1][2], S[2 * ks2 + 1][3]);
      }

      // ---- O += P @ V ----
      const uint32_t* Vs =
          (const uint32_t*)(sm + (buf ? OFF_V1 : OFF_V0)) + g * 36 + c;
#pragma unroll
      for (int ks2 = 0; ks2 < 4; ks2++) {
#pragma unroll
        for (int nt2 = 0; nt2 < 32; nt2++) {
          uint32_t b[2];
          b[0] = Vs[nt2 * 8 * 36 + ks2 * 8];
          b[1] = Vs[nt2 * 8 * 36 + ks2 * 8 + 4];
          mma16(O[nt2], pa[ks2], b);
        }
      }
    }
    __syncthreads();
  }

  // ---- epilogue: O / l -> half, scattered to original rows ----
  const float il0 = 1.0f / l0;
  const float il1 = 1.0f / l1;
  __half* opA = atth + ((size_t)z * 4096 + qiA) * 256;
  __half* opB = atth + ((size_t)z * 4096 + qiB) * 256;
#pragma unroll
  for (int nt2 = 0; nt2 < 32; nt2++) {
    const int col = nt2 * 8 + c * 2;
    store2(opA + col, O[nt2][0] * il0, O[nt2][1] * il0);
    store2(opB + col, O[nt2][2] * il1, O[nt2][3] * il1);
  }
}

// ---------------------------------------------------------------------------
// fp32 -> fp16 conversion
// ---------------------------------------------------------------------------
__global__ __launch_bounds__(256) void cvt_kernel(
    const float* __restrict__ s, __half* __restrict__ d, int n4) {
  int i = blockIdx.x * blockDim.x + threadIdx.x;
  if (i < n4) {
    float4 f = ((const float4*)s)[i];
    ((__half2*)d)[2 * i] = __floats2half2_rn(f.x, f.y);
    ((__half2*)d)[2 * i + 1] = __floats2half2_rn(f.z, f.w);
  }
}

// ---------------------------------------------------------------------------
// Batched transpose (half): vt[b][n][k] = v[b][k][n]
// ---------------------------------------------------------------------------
__global__ __launch_bounds__(256) void transpose_h(
    const __half* __restrict__ v, __half* __restrict__ vt) {
  __shared__ __half t[32][33];
  const int b = blockIdx.z;
  const int k0 = blockIdx.x * 32;
  const int n0 = blockIdx.y * 32;
  const int tx = threadIdx.x & 31;
  const int ty = threadIdx.x >> 5;
  const __half* src = v + (size_t)b * 4096 * 256;
  __half* dst = vt + (size_t)b * 256 * 4096;
#pragma unroll
  for (int i = 0; i < 32; i += 8)
    t[ty + i][tx] = src[(size_t)(k0 + ty + i) * 256 + n0 + tx];
  __syncthreads();
#pragma unroll
  for (int i = 0; i < 32; i += 8)
    dst[(size_t)(n0 + ty + i) * 4096 + k0 + tx] = t[tx][ty + i];
}

// ---------------------------------------------------------------------------
// Launch
// ---------------------------------------------------------------------------
extern "C" void kernel_launch(void* const* d_in, const int* in_sizes, int n_in,
                              void* d_out, int out_size) {
  const float* queries = (const float*)d_in[0];
  const float* keys    = (const float*)d_in[1];
  const float* values  = (const float*)d_in[2];
  const int*   mask    = (const int*)d_in[3];
  const float* Wq = (const float*)d_in[4];
  const float* bq = (const float*)d_in[5];
  const float* Wk = (const float*)d_in[6];
  const float* bk = (const float*)d_in[7];
  const float* Wv = (const float*)d_in[8];
  const float* bv = (const float*)d_in[9];
  const float* Wo = (const float*)d_in[10];
  const float* bo = (const float*)d_in[11];
  float* out = (float*)d_out;

  __half *xq, *xk, *xv, *wq, *wk, *wv, *wo;
  __half *qh, *kh, *vh, *vth, *atth;
  int *startp, *permp;
  cudaGetSymbolAddress((void**)&xq, g_xq);
  cudaGetSymbolAddress((void**)&xk, g_xk);
  cudaGetSymbolAddress((void**)&xv, g_xv);
  cudaGetSymbolAddress((void**)&wq, g_wq);
  cudaGetSymbolAddress((void**)&wk, g_wk);
  cudaGetSymbolAddress((void**)&wv, g_wv);
  cudaGetSymbolAddress((void**)&wo, g_wo);
  cudaGetSymbolAddress((void**)&qh, g_qh);
  cudaGetSymbolAddress((void**)&kh, g_kh);
  cudaGetSymbolAddress((void**)&vh, g_vh);
  cudaGetSymbolAddress((void**)&vth, g_vth);
  cudaGetSymbolAddress((void**)&atth, g_atth);
  cudaGetSymbolAddress((void**)&startp, g_start);
  cudaGetSymbolAddress((void**)&permp, g_perm);

  cudaFuncSetAttribute(hgemm<true, __half>,
                       cudaFuncAttributeMaxDynamicSharedMemorySize, GEMM_SMEM);
  cudaFuncSetAttribute(hgemm<true, float>,
                       cudaFuncAttributeMaxDynamicSharedMemorySize, GEMM_SMEM);
  cudaFuncSetAttribute(flash_attn,
                       cudaFuncAttributeMaxDynamicSharedMemorySize, FLASH_SMEM);

  dim3 blk(256);

  // query-length sort (perm per batch)
  sort_hist_scan<<<4, 1024>>>(mask, startp);
  sort_scatter<<<dim3(16, 4), blk>>>(mask, startp, permp);

  // fp32 -> fp16
  const int NTOK4 = 4 * 4096 * 256 / 4;
  cvt_kernel<<<(NTOK4 + 255) / 256, blk>>>(queries, xq, NTOK4);
  cvt_kernel<<<(NTOK4 + 255) / 256, blk>>>(keys, xk, NTOK4);
  cvt_kernel<<<(NTOK4 + 255) / 256, blk>>>(values, xv, NTOK4);
  const int NW4 = 65536 / 4;
  cvt_kernel<<<(NW4 + 255) / 256, blk>>>(Wq, wq, NW4);
  cvt_kernel<<<(NW4 + 255) / 256, blk>>>(Wk, wk, NW4);
  cvt_kernel<<<(NW4 + 255) / 256, blk>>>(Wv, wv, NW4);
  cvt_kernel<<<(NW4 + 255) / 256, blk>>>(Wo, wo, NW4);

  // Projections -> half
  dim3 gProj(2, 128, 1);
  hgemm<true, __half><<<gProj, blk, GEMM_SMEM>>>(
      xq, wq, bq, qh, 256, 256, 256, 256, 0, 0, 0);
  hgemm<true, __half><<<gProj, blk, GEMM_SMEM>>>(
      xk, wk, bk, kh, 256, 256, 256, 256, 0, 0, 0);
  hgemm<true, __half><<<gProj, blk, GEMM_SMEM>>>(
      xv, wv, bv, vh, 256, 256, 256, 256, 0, 0, 0);

  // vT for flash V tiles
  transpose_h<<<dim3(128, 8, 4), blk>>>(vh, vth);

  // Fused attention (length-sorted scheduling)
  flash_attn<<<dim3(32, 4, 1), blk, FLASH_SMEM>>>(qh, kh, vth, mask, permp, atth);

  // Output projection -> fp32
  hgemm<true, float><<<gProj, blk, GEMM_SMEM>>>(
      atth, wo, bo, out, 256, 256, 256, 256, 0, 0, 0);
}

// round 14
// speedup vs baseline: 1.4681x; 1.2323x over previous
#include <cuda_runtime.h>
#include <cuda_fp16.h>
#include <cstdint>
#include <math.h>

// ---------------------------------------------------------------------------
// B=4, Q=K=4096, D=IN=256.
// R13 = R11 (sorted queries) + split-KV flash (split=2) + partial-combine.
// Rationale: flash wallclock = slowest CTA (one wave). Sorting cut total work
// but not the critical path. Splitting keys across 2 CTAs halves the longest
// CTA; sorting makes total work ~52% so 256 CTAs on 148 SMs balance out.
// ---------------------------------------------------------------------------

#define SPLIT 2

__device__ __half g_xq[4u * 4096u * 256u];
__device__ __half g_xk[4u * 4096u * 256u];
__device__ __half g_xv[4u * 4096u * 256u];
__device__ __half g_wq[65536], g_wk[65536], g_wv[65536], g_wo[65536];
__device__ __half g_qh[4u * 4096u * 256u];
__device__ __half g_kh[4u * 4096u * 256u];
__device__ __half g_vh[4u * 4096u * 256u];
__device__ __half g_vth[4u * 4096u * 256u];
__device__ __half g_atth[4u * 4096u * 256u];
__device__ int g_start[4 * 4096];
__device__ int g_perm[4 * 4096];
__device__ float g_pO[(size_t)SPLIT * 4u * 4096u * 256u];  // unnormalized O
__device__ float g_pM[SPLIT * 16384];
__device__ float g_pL[SPLIT * 16384];

// ======================= helpers =======================
__device__ __forceinline__ uint32_t smem_u32(const void* p) {
  uint32_t a;
  asm("{ .reg .u64 t; cvta.to.shared.u64 t, %1; cvt.u32.u64 %0, t; }"
      : "=r"(a) : "l"(p));
  return a;
}
__device__ __forceinline__ void cp16(uint32_t s, const void* g) {
  asm volatile("cp.async.cg.shared.global [%0], [%1], 16;\n" ::"r"(s), "l"(g));
}
__device__ __forceinline__ void cp_commit() {
  asm volatile("cp.async.commit_group;\n" ::: "memory");
}
template <int N>
__device__ __forceinline__ void cp_wait() {
  asm volatile("cp.async.wait_group %0;\n" ::"n"(N) : "memory");
}
__device__ __forceinline__ void mma16(float* d, const uint32_t* a, const uint32_t* b) {
  asm volatile(
      "mma.sync.aligned.m16n8k16.row.col.f32.f16.f16.f32 "
      "{%0,%1,%2,%3}, {%4,%5,%6,%7}, {%8,%9}, {%0,%1,%2,%3};"
      : "+f"(d[0]), "+f"(d[1]), "+f"(d[2]), "+f"(d[3])
      : "r"(a[0]), "r"(a[1]), "r"(a[2]), "r"(a[3]), "r"(b[0]), "r"(b[1]));
}
__device__ __forceinline__ uint32_t pack_half2(float a, float b) {
  __half2 h = __floats2half2_rn(a, b);
  return *(uint32_t*)&h;
}
__device__ __forceinline__ void store2(float* p, float d0, float d1) {
  float2 v; v.x = d0; v.y = d1;
  *(float2*)p = v;
}
__device__ __forceinline__ void store2(__half* p, float d0, float d1) {
  *(__half2*)p = __floats2half2_rn(d0, d1);
}

// ---------------------------------------------------------------------------
// Counting sort of queries by mask length (per batch). Ascending.
// ---------------------------------------------------------------------------
__global__ __launch_bounds__(1024) void sort_hist_scan(
    const int* __restrict__ mask, int* __restrict__ start) {
  __shared__ int hist[4096];
  __shared__ int sums[1024];
  __shared__ int sums2[1024];
  const int z = blockIdx.x;
  const int t = threadIdx.x;
#pragma unroll
  for (int i = 0; i < 4; i++) hist[t + i * 1024] = 0;
  __syncthreads();
#pragma unroll
  for (int i = 0; i < 4; i++)
    atomicAdd(&hist[mask[z * 4096 + t + i * 1024] - 1], 1);
  __syncthreads();
  const int c0 = hist[4 * t], c1 = hist[4 * t + 1];
  const int c2 = hist[4 * t + 2], c3 = hist[4 * t + 3];
  sums[t] = c0 + c1 + c2 + c3;
  __syncthreads();
  int* src = sums;
  int* dst = sums2;
  for (int off = 1; off < 1024; off <<= 1) {
    int v = src[t];
    if (t >= off) v += src[t - off];
    dst[t] = v;
    __syncthreads();
    int* tmp = src; src = dst; dst = tmp;
  }
  const int excl = (t == 0) ? 0 : src[t - 1];
  start[z * 4096 + 4 * t] = excl;
  start[z * 4096 + 4 * t + 1] = excl + c0;
  start[z * 4096 + 4 * t + 2] = excl + c0 + c1;
  start[z * 4096 + 4 * t + 3] = excl + c0 + c1 + c2;
}

__global__ __launch_bounds__(256) void sort_scatter(
    const int* __restrict__ mask, int* __restrict__ start,
    int* __restrict__ perm) {
  const int z = blockIdx.y;
  const int i = blockIdx.x * 256 + threadIdx.x;
  const int len = mask[z * 4096 + i];
  const int pos = atomicAdd(&start[z * 4096 + len - 1], 1);
  perm[z * 4096 + pos] = i;
}

// ---------------------------------------------------------------------------
// fp16 GEMM (proven): C[M,N] = A[M,Kd] @ B[N,Kd]^T (+ bias)
// ---------------------------------------------------------------------------
#define S32 20
#define TILE_WORDS (128 * S32)
#define STAGE_BYTES (2 * TILE_WORDS * 4)
#define GEMM_SMEM (2 * STAGE_BYTES)

template <bool BIAS, typename OutT>
__global__ void __launch_bounds__(256, 2) hgemm(
    const __half* __restrict__ A, const __half* __restrict__ B,
    const float* __restrict__ bias, OutT* __restrict__ C,
    int Kd, int ldA, int ldB, int ldC,
    long long sA, long long sB, long long sC) {
  extern __shared__ char dyn_smem[];
  const uint32_t smem_base = smem_u32(dyn_smem);
  const int tid = threadIdx.x;
  const int lane = tid & 31;
  const int wid = tid >> 5;
  const int wm = wid & 1;
  const int wn = wid >> 1;
  const long long z = blockIdx.z;
  const int bm = blockIdx.y * 128;
  const int bn = blockIdx.x * 128;

  const __half* gA = A + z * sA + (size_t)bm * ldA;
  const __half* gB = B + z * sB + (size_t)bn * ldB;

  float acc[4][4][4];
#pragma unroll
  for (int i = 0; i < 4; i++)
#pragma unroll
    for (int j = 0; j < 4; j++)
#pragma unroll
      for (int p = 0; p < 4; p++) acc[i][j][p] = 0.0f;

  const int ldRow = tid & 127;
  const bool isB = tid >= 128;
  const __half* gRowBase = (isB ? gB : gA);
  const int ldLd = isB ? ldB : ldA;
  const uint32_t sRowOff = (isB ? STAGE_BYTES / 2 : 0) + ldRow * (S32 * 4);

  auto load_tiles = [&](int stage, int k0) {
    const uint32_t s0 = smem_base + stage * STAGE_BYTES + sRowOff;
    const __half* g0 = gRowBase + (size_t)ldRow * ldLd + k0;
#pragma unroll
    for (int ch = 0; ch < 4; ch++) cp16(s0 + ch * 16, g0 + ch * 8);
    cp_commit();
  };

  const int g = lane >> 2;
  const int c = lane & 3;

  const int KT = Kd >> 5;
  load_tiles(0, 0);
  for (int it = 0; it < KT; ++it) {
    const int buf = it & 1;
    if (it + 1 < KT) {
      load_tiles(buf ^ 1, (it + 1) << 5);
      cp_wait<1>();
    } else {
      cp_wait<0>();
    }
    __syncthreads();

    const uint32_t* As32 = (const uint32_t*)(dyn_smem + buf * STAGE_BYTES);
    const uint32_t* Bs32 = As32 + TILE_WORDS;

#pragma unroll
    for (int kk = 0; kk < 2; ++kk) {
      const int ko = kk * 8;
      uint32_t af[4][4], bf[4][2];
#pragma unroll
      for (int mt = 0; mt < 4; mt++) {
        const int base = (wm * 64 + mt * 16 + g) * S32 + c + ko;
        af[mt][0] = As32[base];
        af[mt][1] = As32[base + 8 * S32];
        af[mt][2] = As32[base + 4];
        af[mt][3] = As32[base + 8 * S32 + 4];
      }
#pragma unroll
      for (int nt = 0; nt < 4; nt++) {
        const int base = (wn * 32 + nt * 8 + g) * S32 + c + ko;
        bf[nt][0] = Bs32[base];
        bf[nt][1] = Bs32[base + 4];
      }
#pragma unroll
      for (int mt = 0; mt < 4; mt++)
#pragma unroll
        for (int nt = 0; nt < 4; nt++) mma16(acc[mt][nt], af[mt], bf[nt]);
    }
    __syncthreads();
  }

  OutT* Cz = C + z * sC;
  const int c2 = c * 2;
#pragma unroll
  for (int mt = 0; mt < 4; mt++) {
    const int row0 = bm + wm * 64 + mt * 16 + g;
#pragma unroll
    for (int nt = 0; nt < 4; nt++) {
      const int col = bn + wn * 32 + nt * 8 + c2;
      float d0 = acc[mt][nt][0], d1 = acc[mt][nt][1];
      float d2 = acc[mt][nt][2], d3 = acc[mt][nt][3];
      if (BIAS) {
        const float b0 = bias[col], b1 = bias[col + 1];
        d0 += b0; d1 += b1; d2 += b0; d3 += b1;
      }
      store2(Cz + (size_t)row0 * ldC + col, d0, d1);
      store2(Cz + (size_t)(row0 + 8) * ldC + col, d2, d3);
    }
  }
}

// ---------------------------------------------------------------------------
// Split-KV flash attention with length-sorted query permutation.
// Grid (32, 4, SPLIT). CTA: 128 permuted q-rows x keys in its chunk.
// Writes unnormalized partials (pO fp32, pM, pL) per row per split.
// qt = 31 - blockIdx.x: longest (ascending-sorted) qtiles scheduled first.
// ---------------------------------------------------------------------------
#define OFF_Q 0
#define OFF_K0 (128 * 528)
#define OFF_K1 (OFF_K0 + 64 * 528)
#define OFF_V0 (OFF_K1 + 64 * 528)
#define OFF_V1 (OFF_V0 + 256 * 144)
#define FLASH_SMEM (OFF_V1 + 256 * 144)

__global__ void __launch_bounds__(256, 1) flash_attn(
    const __half* __restrict__ qh, const __half* __restrict__ kh,
    const __half* __restrict__ vth, const int* __restrict__ mask,
    const int* __restrict__ perm, float* __restrict__ pO,
    float* __restrict__ pM, float* __restrict__ pL) {
  extern __shared__ char sm[];
  const uint32_t sb = smem_u32(sm);
  const int tid = threadIdx.x;
  const int lane = tid & 31;
  const int w = tid >> 5;
  const int g = lane >> 2;
  const int c = lane & 3;
  const int z = blockIdx.y;
  const int split = blockIdx.z;
  const int qt = 31 - blockIdx.x;  // longest first
  const int bm = qt * 128;

  const __half* qp = qh + (size_t)z * 4096 * 256;
  const __half* kp = kh + (size_t)z * 4096 * 256;
  const __half* vp = vth + (size_t)z * 256 * 4096;
  const int* permz = perm + z * 4096 + bm;
  const size_t pbase = (size_t)split * 16384 + (size_t)z * 4096;

  __shared__ int s_ctamax;
  if (tid == 0) s_ctamax = 0;
  __syncthreads();

  const int qiA = permz[w * 16 + g];
  const int qiB = permz[w * 16 + 8 + g];
  const int lenA = mask[z * 4096 + qiA];
  const int lenB = mask[z * 4096 + qiB];
  int wmax = max(lenA, lenB);
#pragma unroll
  for (int o = 4; o < 32; o <<= 1) wmax = max(wmax, __shfl_xor_sync(0xffffffffu, wmax, o));
  if (lane == 0) atomicMax(&s_ctamax, wmax);
  __syncthreads();

  const int t0 = split * (2048 / 64);
  const int tend = min((split + 1) * (2048 / 64), (s_ctamax + 63) >> 6);
  if (tend <= t0) {
    // nothing in this chunk for any row: sentinel partials (weight 0 in combine)
    if (tid < 128) {
      const int qi = permz[tid];
      pM[pbase + qi] = -1e30f;
      pL[pbase + qi] = 0.0f;
    }
    return;
  }

  // Q tile (gathered): 128 rows x 512B (stride 528B)
#pragma unroll
  for (int i = 0; i < 16; i++) {
    const int idx = tid + i * 256;
    const int row = idx >> 5, ch = idx & 31;
    const int qrow = permz[row];
    cp16(sb + OFF_Q + row * 528 + ch * 16, qp + (size_t)qrow * 256 + ch * 8);
  }
  cp_commit();

  auto load_kv = [&](int stage, int kt) {
    const uint32_t ko = sb + (stage ? OFF_K1 : OFF_K0);
    const uint32_t vo = sb + (stage ? OFF_V1 : OFF_V0);
#pragma unroll
    for (int i = 0; i < 8; i++) {
      const int idx = tid + i * 256;
      const int row = idx >> 5, ch = idx & 31;
      cp16(ko + row * 528 + ch * 16, kp + (size_t)(kt * 64 + row) * 256 + ch * 8);
    }
#pragma unroll
    for (int i = 0; i < 8; i++) {
      const int idx = tid + i * 256;
      const int row = idx >> 3, ch = idx & 7;
      cp16(vo + row * 144 + ch * 16, vp + (size_t)row * 4096 + kt * 64 + ch * 8);
    }
    cp_commit();
  };

  load_kv(0, t0);

  float O[32][4];
#pragma unroll
  for (int i = 0; i < 32; i++)
#pragma unroll
    for (int j = 0; j < 4; j++) O[i][j] = 0.0f;
  float m0 = -1e30f, m1 = -1e30f, l0 = 0.0f, l1 = 0.0f;

  for (int kt = t0; kt < tend; kt++) {
    const int buf = kt & 1;
    if (kt + 1 < tend) {
      load_kv(buf ^ 1, kt + 1);
      cp_wait<1>();
    } else {
      cp_wait<0>();
    }
    __syncthreads();

    if (kt * 64 < wmax) {
      // ---- S = Q @ K^T ----
      float S[8][4];
#pragma unroll
      for (int nt = 0; nt < 8; nt++)
#pragma unroll
        for (int j = 0; j < 4; j++) S[nt][j] = 0.0f;

      const uint32_t* Qs = (const uint32_t*)(sm + OFF_Q) + (w * 16 + g) * 132 + c;
      const uint32_t* Ks =
          (const uint32_t*)(sm + (buf ? OFF_K1 : OFF_K0)) + g * 132 + c;
#pragma unroll
      for (int ks = 0; ks < 16; ks++) {
        uint32_t a[4];
        a[0] = Qs[ks * 8];
        a[1] = Qs[ks * 8 + 8 * 132];
        a[2] = Qs[ks * 8 + 4];
        a[3] = Qs[ks * 8 + 8 * 132 + 4];
#pragma unroll
        for (int nt = 0; nt < 8; nt++) {
          uint32_t b[2];
          b[0] = Ks[nt * 8 * 132 + ks * 8];
          b[1] = Ks[nt * 8 * 132 + ks * 8 + 4];
          mma16(S[nt], a, b);
        }
      }

      // ---- mask + scale(1/16) + online softmax ----
      const int kb = kt * 64;
      float tmax0 = -1e30f, tmax1 = -1e30f;
#pragma unroll
      for (int nt = 0; nt < 8; nt++) {
        const int col0 = kb + nt * 8 + c * 2;
        const int col1 = col0 + 1;
        float s00 = (col0 < lenA) ? S[nt][0] * 0.0625f : -1e30f;
        float s01 = (col1 < lenA) ? S[nt][1] * 0.0625f : -1e30f;
        float s10 = (col0 < lenB) ? S[nt][2] * 0.0625f : -1e30f;
        float s11 = (col1 < lenB) ? S[nt][3] * 0.0625f : -1e30f;
        S[nt][0] = s00; S[nt][1] = s01; S[nt][2] = s10; S[nt][3] = s11;
        tmax0 = fmaxf(tmax0, fmaxf(s00, s01));
        tmax1 = fmaxf(tmax1, fmaxf(s10, s11));
      }
      tmax0 = fmaxf(tmax0, __shfl_xor_sync(0xffffffffu, tmax0, 1));
      tmax0 = fmaxf(tmax0, __shfl_xor_sync(0xffffffffu, tmax0, 2));
      tmax1 = fmaxf(tmax1, __shfl_xor_sync(0xffffffffu, tmax1, 1));
      tmax1 = fmaxf(tmax1, __shfl_xor_sync(0xffffffffu, tmax1, 2));

      const float mn0 = fmaxf(m0, tmax0), mn1 = fmaxf(m1, tmax1);
      const float al0 = __expf(m0 - mn0), al1 = __expf(m1 - mn1);
      m0 = mn0; m1 = mn1;

      float sum0 = 0.0f, sum1 = 0.0f;
#pragma unroll
      for (int nt = 0; nt < 8; nt++) {
        S[nt][0] = __expf(S[nt][0] - mn0);
        S[nt][1] = __expf(S[nt][1] - mn0);
        S[nt][2] = __expf(S[nt][2] - mn1);
        S[nt][3] = __expf(S[nt][3] - mn1);
        sum0 += S[nt][0] + S[nt][1];
        sum1 += S[nt][2] + S[nt][3];
      }
      sum0 += __shfl_xor_sync(0xffffffffu, sum0, 1);
      sum0 += __shfl_xor_sync(0xffffffffu, sum0, 2);
      sum1 += __shfl_xor_sync(0xffffffffu, sum1, 1);
      sum1 += __shfl_xor_sync(0xffffffffu, sum1, 2);
      l0 = l0 * al0 + sum0;
      l1 = l1 * al1 + sum1;

#pragma unroll
      for (int nt2 = 0; nt2 < 32; nt2++) {
        O[nt2][0] *= al0; O[nt2][1] *= al0;
        O[nt2][2] *= al1; O[nt2][3] *= al1;
      }

      // ---- P fragments (C-layout -> A-fragment) ----
      uint32_t pa[4][4];
#pragma unroll
      for (int ks2 = 0; ks2 < 4; ks2++) {
        pa[ks2][0] = pack_half2(S[2 * ks2][0], S[2 * ks2][1]);
        pa[ks2][1] = pack_half2(S[2 * ks2][2], S[2 * ks2][3]);
        pa[ks2][2] = pack_half2(S[2 * ks2 + 1][0], S[2 * ks2 + 1][1]);
        pa[ks2][3] = pack_half2(S[2 * ks2 + 1][2], S[2 * ks2 + 1][3]);
      }

      // ---- O += P @ V ----
      const uint32_t* Vs =
          (const uint32_t*)(sm + (buf ? OFF_V1 : OFF_V0)) + g * 36 + c;
#pragma unroll
      for (int ks2 = 0; ks2 < 4; ks2++) {
#pragma unroll
        for (int nt2 = 0; nt2 < 32; nt2++) {
          uint32_t b[2];
          b[0] = Vs[nt2 * 8 * 36 + ks2 * 8];
          b[1] = Vs[nt2 * 8 * 36 + ks2 * 8 + 4];
          mma16(O[nt2], pa[ks2], b);
        }
      }
    }
    __syncthreads();
  }

  // ---- epilogue: unnormalized partials, scattered by original row ----
  float* opA = pO + (pbase + qiA) * 256;
  float* opB = pO + (pbase + qiB) * 256;
#pragma unroll
  for (int nt2 = 0; nt2 < 32; nt2++) {
    const int col = nt2 * 8 + c * 2;
    store2(opA + col, O[nt2][0], O[nt2][1]);
    store2(opB + col, O[nt2][2], O[nt2][3]);
  }
  if (c == 0) {
    pM[pbase + qiA] = m0; pL[pbase + qiA] = l0;
    pM[pbase + qiB] = m1; pL[pbase + qiB] = l1;
  }
}

// ---------------------------------------------------------------------------
// Combine the SPLIT partials per row -> half atth.
// Grid 4096 blocks x 256 threads; each block 4 rows, each thread 4 cols.
// ---------------------------------------------------------------------------
__global__ __launch_bounds__(256) void combine_kernel(
    const float* __restrict__ pO, const float* __restrict__ pM,
    const float* __restrict__ pL, __half* __restrict__ atth) {
  const int row = blockIdx.x * 4 + (threadIdx.x >> 6);
  const int t = threadIdx.x & 63;
  const float m0 = pM[row], m1 = pM[16384 + row];
  const float l0 = pL[row], l1 = pL[16384 + row];
  const float ms = fmaxf(m0, m1);
  const float w0 = __expf(m0 - ms), w1 = __expf(m1 - ms);
  const float inv = 1.0f / (l0 * w0 + l1 * w1);
  const float f0 = w0 * inv, f1 = w1 * inv;
  const float4 a = ((const float4*)(pO + (size_t)row * 256))[t];
  const float4 b = ((const float4*)(pO + ((size_t)(16384 + row)) * 256))[t];
  __half2 h0 = __floats2half2_rn(a.x * f0 + b.x * f1, a.y * f0 + b.y * f1);
  __half2 h1 = __floats2half2_rn(a.z * f0 + b.z * f1, a.w * f0 + b.w * f1);
  ((__half2*)(atth + (size_t)row * 256))[2 * t] = h0;
  ((__half2*)(atth + (size_t)row * 256))[2 * t + 1] = h1;
}

// ---------------------------------------------------------------------------
// fp32 -> fp16: 3 equal-size input jobs in one launch; 4 weight jobs in one.
// ---------------------------------------------------------------------------
__global__ __launch_bounds__(256) void cvt3_kernel(
    const float* s0, __half* d0, const float* s1, __half* d1,
    const float* s2, __half* d2, int n4) {
  const float* ss[3] = {s0, s1, s2};
  __half* dd[3] = {d0, d1, d2};
  const int j = blockIdx.y;
  const int i = blockIdx.x * blockDim.x + threadIdx.x;
  if (i < n4) {
    float4 f = ((const float4*)ss[j])[i];
    ((__half2*)dd[j])[2 * i] = __floats2half2_rn(f.x, f.y);
    ((__half2*)dd[j])[2 * i + 1] = __floats2half2_rn(f.z, f.w);
  }
}
__global__ __launch_bounds__(256) void cvt4_kernel(
    const float* s0, __half* d0, const float* s1, __half* d1,
    const float* s2, __half* d2, const float* s3, __half* d3, int n4) {
  const float* ss[4] = {s0, s1, s2, s3};
  __half* dd[4] = {d0, d1, d2, d3};
  const int j = blockIdx.y;
  const int i = blockIdx.x * blockDim.x + threadIdx.x;
  if (i < n4) {
    float4 f = ((const float4*)ss[j])[i];
    ((__half2*)dd[j])[2 * i] = __floats2half2_rn(f.x, f.y);
    ((__half2*)dd[j])[2 * i + 1] = __floats2half2_rn(f.z, f.w);
  }
}

// ---------------------------------------------------------------------------
// Batched transpose (half): vt[b][n][k] = v[b][k][n]
// ---------------------------------------------------------------------------
__global__ __launch_bounds__(256) void transpose_h(
    const __half* __restrict__ v, __half* __restrict__ vt) {
  __shared__ __half t[32][33];
  const int b = blockIdx.z;
  const int k0 = blockIdx.x * 32;
  const int n0 = blockIdx.y * 32;
  const int tx = threadIdx.x & 31;
  const int ty = threadIdx.x >> 5;
  const __half* src = v + (size_t)b * 4096 * 256;
  __half* dst = vt + (size_t)b * 256 * 4096;
#pragma unroll
  for (int i = 0; i < 32; i += 8)
    t[ty + i][tx] = src[(size_t)(k0 + ty + i) * 256 + n0 + tx];
  __syncthreads();
#pragma unroll
  for (int i = 0; i < 32; i += 8)
    dst[(size_t)(n0 + ty + i) * 4096 + k0 + tx] = t[tx][ty + i];
}

// ---------------------------------------------------------------------------
// Launch
// ---------------------------------------------------------------------------
extern "C" void kernel_launch(void* const* d_in, const int* in_sizes, int n_in,
                              void* d_out, int out_size) {
  const float* queries = (const float*)d_in[0];
  const float* keys    = (const float*)d_in[1];
  const float* values  = (const float*)d_in[2];
  const int*   mask    = (const int*)d_in[3];
  const float* Wq = (const float*)d_in[4];
  const float* bq = (const float*)d_in[5];
  const float* Wk = (const float*)d_in[6];
  const float* bk = (const float*)d_in[7];
  const float* Wv = (const float*)d_in[8];
  const float* bv = (const float*)d_in[9];
  const float* Wo = (const float*)d_in[10];
  const float* bo = (const float*)d_in[11];
  float* out = (float*)d_out;

  __half *xq, *xk, *xv, *wq, *wk, *wv, *wo;
  __half *qh, *kh, *vh, *vth, *atth;
  int *startp, *permp;
  float *pO, *pM, *pL;
  cudaGetSymbolAddress((void**)&xq, g_xq);
  cudaGetSymbolAddress((void**)&xk, g_xk);
  cudaGetSymbolAddress((void**)&xv, g_xv);
  cudaGetSymbolAddress((void**)&wq, g_wq);
  cudaGetSymbolAddress((void**)&wk, g_wk);
  cudaGetSymbolAddress((void**)&wv, g_wv);
  cudaGetSymbolAddress((void**)&wo, g_wo);
  cudaGetSymbolAddress((void**)&qh, g_qh);
  cudaGetSymbolAddress((void**)&kh, g_kh);
  cudaGetSymbolAddress((void**)&vh, g_vh);
  cudaGetSymbolAddress((void**)&vth, g_vth);
  cudaGetSymbolAddress((void**)&atth, g_atth);
  cudaGetSymbolAddress((void**)&startp, g_start);
  cudaGetSymbolAddress((void**)&permp, g_perm);
  cudaGetSymbolAddress((void**)&pO, g_pO);
  cudaGetSymbolAddress((void**)&pM, g_pM);
  cudaGetSymbolAddress((void**)&pL, g_pL);

  cudaFuncSetAttribute(hgemm<true, __half>,
                       cudaFuncAttributeMaxDynamicSharedMemorySize, GEMM_SMEM);
  cudaFuncSetAttribute(hgemm<true, float>,
                       cudaFuncAttributeMaxDynamicSharedMemorySize, GEMM_SMEM);
  cudaFuncSetAttribute(flash_attn,
                       cudaFuncAttributeMaxDynamicSharedMemorySize, FLASH_SMEM);

  dim3 blk(256);

  // query-length sort (perm per batch)
  sort_hist_scan<<<4, 1024>>>(mask, startp);
  sort_scatter<<<dim3(16, 4), blk>>>(mask, startp, permp);

  // fp32 -> fp16 (2 launches)
  const int NTOK4 = 4 * 4096 * 256 / 4;
  const int NW4 = 65536 / 4;
  cvt3_kernel<<<dim3(NTOK4 / 256, 3), blk>>>(queries, xq, keys, xk, values, xv, NTOK4);
  cvt4_kernel<<<dim3(NW4 / 256, 4), blk>>>(Wq, wq, Wk, wk, Wv, wv, Wo, wo, NW4);

  // Projections -> half
  dim3 gProj(2, 128, 1);
  hgemm<true, __half><<<gProj, blk, GEMM_SMEM>>>(
      xq, wq, bq, qh, 256, 256, 256, 256, 0, 0, 0);
  hgemm<true, __half><<<gProj, blk, GEMM_SMEM>>>(
      xk, wk, bk, kh, 256, 256, 256, 256, 0, 0, 0);
  hgemm<true, __half><<<gProj, blk, GEMM_SMEM>>>(
      xv, wv, bv, vh, 256, 256, 256, 256, 0, 0, 0);

  // vT for flash V tiles
  transpose_h<<<dim3(128, 8, 4), blk>>>(vh, vth);

  // Split-KV fused attention (sorted scheduling, longest first)
  flash_attn<<<dim3(32, 4, SPLIT), blk, FLASH_SMEM>>>(
      qh, kh, vth, mask, permp, pO, pM, pL);

  // Combine partials -> atth (half)
  combine_kernel<<<4096, blk>>>(pO, pM, pL, atth);

  // Output projection -> fp32
  hgemm<true, float><<<gProj, blk, GEMM_SMEM>>>(
      atth, wo, bo, out, 256, 256, 256, 256, 0, 0, 0);
}